// round 15
// baseline (speedup 1.0000x reference)
#include <cuda_runtime.h>
#include <cstdint>

#define BB 8
#define NN 512
#define KK 30
#define HAA 20
#define HP 22
#define EMB 484
#define KSZ 9
#define MAXM 30
#define NSLOT (BB*MAXM)      // 240
#define NSEQ 99
#define CIT 4356             // EMB*KSZ
#define CIC 11               // conv ci chunk
#define NCH 44               // conv chunks
#define MCIC 11              // mlp ci chunk
#define MNCH 44              // mlp chunks
#define PAIRS 16             // pairs per conv block
#define ROWS 16              // rows per mlp block
#define CHALF 242            // c-split: 2 x 242 = 484

// ---- f32x2 packed helpers (sm_10x) ----
#define FMA2(acc, x2, w2) asm("fma.rn.f32x2 %0, %1, %2, %0;" : "+l"(acc) : "l"(x2), "l"(w2))
#define BCAST2(d, w)      asm("mov.b64 %0, {%1, %1};" : "=l"(d) : "f"(w))
#define UNPACK2(lo, hi, s) asm("mov.b64 {%0, %1}, %2;" : "=f"(lo), "=f"(hi) : "l"(s))
// 16B shared load directly into two packed f32x2 operands (requires 16B-aligned addr)
#define LDS2x64(a, b, addr) asm("ld.shared.v2.u64 {%0, %1}, [%2];" : "=l"(a), "=l"(b) : "r"(addr))

// ---------------- scratch (static device globals; no allocation) ----------------
__device__ float g_Wtf[CIT*EMB];     // [(ci*9+t)][c]
__device__ float g_Wta[CIT*EMB];
__device__ float g_W1t[EMB*EMB];     // [ci][c]
__device__ float g_W2t[EMB*EMB];
__device__ float g_linv[NSLOT*EMB];
__device__ float g_O[NSLOT*EMB];
__device__ float g_A[NSLOT*EMB];
__device__ float g_LA[NSLOT*EMB];
__device__ float g_Y1[NSLOT*EMB];
__device__ float g_DDG[(NSLOT+1)*EMB];
__device__ int   g_row[BB*NN];             // dense pos -> rowBase (*EMB, bg row if none)
__device__ int   g_m[BB];
__device__ int   g_cntBT[BB*KSZ];          // per-(b,tap) pair count
__device__ int   g_pairIn[BB*KSZ*MAXM];
__device__ int   g_pairOut[BB*KSZ*MAXM];

// ---------------- K1 fused: transposes + parallel scatter + Y1/DDG init ----------------
#define TB0 2192
#define TB1 4384
#define TB2 4640
#define TB3 4896
#define SCAT_END (TB3 + BB)
#define INIT_END (SCAT_END + NSLOT + 1)
#define PREP_BLOCKS INIT_END

__global__ void k_prep(const float* __restrict__ Wf, const float* __restrict__ Wa,
                       const float* __restrict__ W1, const float* __restrict__ W2,
                       const float* __restrict__ etab, const int* __restrict__ E_idx,
                       const int* __restrict__ mut_pos,
                       const float* __restrict__ b_f, const float* __restrict__ b_a,
                       const float* __restrict__ b1, const float* __restrict__ b2,
                       const float* __restrict__ wddg, const float* __restrict__ bddg) {
    int bx = blockIdx.x;
    int tid = threadIdx.x;

    if (bx >= SCAT_END) {
        int row = bx - SCAT_END;
        float wd = wddg[0], bd = bddg[0];
        for (int c = tid; c < EMB; c += 256) {
            float dinit = b2[c] * wd + bd;
            g_DDG[row * EMB + c] = dinit;
            if (row < NSLOT) g_Y1[row * EMB + c] = b1[c];
        }
        return;
    }

    if (bx < TB3) {
        __shared__ float tile[32][33];
        const float* src; float* dst; int C, xt, yt;
        if (bx < TB0)      { src = Wf; dst = g_Wtf; C = CIT; int i = bx;       xt = i % 137; yt = i / 137; }
        else if (bx < TB1) { src = Wa; dst = g_Wta; C = CIT; int i = bx - TB0; xt = i % 137; yt = i / 137; }
        else if (bx < TB2) { src = W1; dst = g_W1t; C = EMB; int i = bx - TB1; xt = i % 16;  yt = i / 16; }
        else               { src = W2; dst = g_W2t; C = EMB; int i = bx - TB2; xt = i % 16;  yt = i / 16; }
        int tx = tid & 31, ty = tid >> 5;
        int xBase = xt * 32, yBase = yt * 32;
        int x = xBase + tx;
        for (int j = ty; j < 32; j += 8) {
            int y = yBase + j;
            if (y < EMB && x < C) tile[j][tx] = src[y * C + x];
        }
        __syncthreads();
        int ox = yBase + tx;
        for (int j = ty; j < 32; j += 8) {
            int oy = xBase + j;
            if (oy < C && ox < EMB) dst[oy * EMB + ox] = tile[tx][j];
        }
        return;
    }

    // ---- scatter part (256 threads, one block per batch) ----
    int b = bx - TB3;
    __shared__ int win[NN];
    __shared__ int slotArr[NN];
    __shared__ unsigned msk[16];
    __shared__ int cpre[16];
    __shared__ int sPos[MAXM], sSrc[MAXM];
    __shared__ int sM;

    win[tid] = -1; win[tid + 256] = -1;
    if (tid < KSZ) g_cntBT[b * KSZ + tid] = 0;
    __syncthreads();

    int mp = mut_pos[b];
    const int* nb = &E_idx[(b * NN + mp) * KK];
    if (tid < KK) atomicMax(&win[nb[tid]], tid);   // last j wins == max j wins
    __syncthreads();

    int warp = tid >> 5, lane = tid & 31;
    #pragma unroll
    for (int h = 0; h < 2; h++) {
        int chunk = warp + h * 8;
        int l = chunk * 32 + lane;
        unsigned bal = __ballot_sync(0xffffffffu, win[l] >= 0);
        if (lane == 0) msk[chunk] = bal;
    }
    __syncthreads();
    if (tid == 0) {
        int acc = 0;
        for (int i = 0; i < 16; i++) { cpre[i] = acc; acc += __popc(msk[i]); }
        sM = acc; g_m[b] = acc;
    }
    __syncthreads();
    #pragma unroll
    for (int h = 0; h < 2; h++) {
        int chunk = warp + h * 8;
        int l = chunk * 32 + lane;
        int w = win[l];
        int slot = -1;
        if (w >= 0) {
            slot = cpre[chunk] + __popc(msk[chunk] & ((1u << lane) - 1));
            sPos[slot] = l; sSrc[slot] = w;
        }
        slotArr[l] = slot;
        g_row[b * NN + l] = ((slot >= 0) ? (b * MAXM + slot) : NSLOT) * EMB;
    }
    __syncthreads();

    int m = sM;
    for (int c = tid; c < EMB; c += 256) {
        int h0 = c / HP, h1 = c % HP;
        float bfv = b_f[c], bav = b_a[c];
        bool valid = (h0 < HAA) && (h1 < HAA);
        int srcc = h0 * HAA + h1;
        for (int s = 0; s < m; s++) {
            float v = 0.f;
            if (valid)
                v = etab[(size_t)((b * NN + mp) * KK + sSrc[s]) * (HAA * HAA) + srcc];
            int g = (b * MAXM + s) * EMB + c;
            g_linv[g] = v; g_O[g] = bfv; g_A[g] = bav;
        }
    }
    for (int q = tid; q < m * KSZ; q += 256) {
        int s = q / KSZ, t = q % KSZ;
        int p = sPos[s] + t - 4;              // y[l] += W[t] * x[l+t-4]
        if (p >= 0 && p < NN) {
            int si = slotArr[p];
            if (si >= 0) {
                int idx = atomicAdd(&g_cntBT[b * KSZ + t], 1);
                g_pairIn[(b * KSZ + t) * MAXM + idx]  = b * MAXM + si;
                g_pairOut[(b * KSZ + t) * MAXM + idx] = b * MAXM + s;
            }
        }
    }
}

// ---------------- K2: conv — 256 threads, c-split, CIC=11, f32x2 + v2.u64 LDS ----------------
// grid: (pairBlocks, KSZ, NCH*2); z = chunk*2 + cHalf
__global__ void __launch_bounds__(256, 4) k_conv() {
    int t = blockIdx.y;
    int chunk = blockIdx.z >> 1;
    int cHalf = blockIdx.z & 1;
    __shared__ __align__(16) float xs[CIC][PAIRS];   // [k][pair], 64B rows
    __shared__ int cnt[BB];
    __shared__ int pre[BB + 1];
    __shared__ int pin[PAIRS], pout[PAIRS];
    int tid = threadIdx.x;
    if (tid < BB) cnt[tid] = g_cntBT[tid * KSZ + t];
    __syncthreads();
    if (tid == 0) {
        int acc = 0;
        #pragma unroll
        for (int b = 0; b < BB; b++) { pre[b] = acc; acc += cnt[b]; }
        pre[BB] = acc;
    }
    __syncthreads();
    int total = pre[BB];
    int p0 = blockIdx.x * PAIRS;
    if (p0 >= total) return;
    if (tid < PAIRS) {
        int gi = p0 + tid;
        if (gi < total) {
            int b = 0;
            while (gi >= pre[b + 1]) b++;
            int idx = gi - pre[b];
            pin[tid]  = g_pairIn[(b * KSZ + t) * MAXM + idx];
            pout[tid] = g_pairOut[(b * KSZ + t) * MAXM + idx];
        } else { pin[tid] = -1; pout[tid] = -1; }
    }
    __syncthreads();
    int ciBeg = chunk * CIC;
    if (tid < PAIRS * CIC) {
        int i = tid >> 4, s = tid & 15;
        int g = pin[s];
        xs[i][s] = (g >= 0) ? g_linv[g * EMB + ciBeg + i] : 0.f;
    }
    __syncthreads();
    if (tid >= CHALF) return;
    int c = cHalf * CHALF + tid;
    unsigned xsB = (unsigned)__cvta_generic_to_shared(&xs[0][0]);
    unsigned long long aO[8], aA[8];
    #pragma unroll
    for (int p = 0; p < 8; p++) { aO[p] = 0ull; aA[p] = 0ull; }
    const float* wf = &g_Wtf[(ciBeg * KSZ + t) * EMB + c];
    const float* wa = &g_Wta[(ciBeg * KSZ + t) * EMB + c];
    float wfv[CIC], wav[CIC];
    #pragma unroll
    for (int k = 0; k < CIC; k++) {
        wfv[k] = wf[k * (KSZ * EMB)];
        wav[k] = wa[k * (KSZ * EMB)];
    }
    #pragma unroll
    for (int k = 0; k < CIC; k++) {
        unsigned long long wf2, wa2;
        BCAST2(wf2, wfv[k]);
        BCAST2(wa2, wav[k]);
        unsigned rowB = xsB + k * (PAIRS * 4);
        #pragma unroll
        for (int j = 0; j < 4; j++) {
            unsigned long long x0, x1;
            LDS2x64(x0, x1, rowB + j * 16);
            FMA2(aO[j * 2],     x0, wf2);
            FMA2(aO[j * 2 + 1], x1, wf2);
            FMA2(aA[j * 2],     x0, wa2);
            FMA2(aA[j * 2 + 1], x1, wa2);
        }
    }
    #pragma unroll
    for (int p = 0; p < 8; p++) {
        float olo, ohi, alo, ahi;
        UNPACK2(olo, ohi, aO[p]);
        UNPACK2(alo, ahi, aA[p]);
        int g0 = pout[p * 2], g1 = pout[p * 2 + 1];
        if (g0 >= 0) { atomicAdd(&g_O[g0 * EMB + c], olo); atomicAdd(&g_A[g0 * EMB + c], alo); }
        if (g1 >= 0) { atomicAdd(&g_O[g1 * EMB + c], ohi); atomicAdd(&g_A[g1 * EMB + c], ahi); }
    }
}

// ---------------- K3: register-resident masked softmax -> relu(la) ----------------
__global__ void k_softmax() {
    int b = blockIdx.x;
    int c = blockIdx.y * 128 + threadIdx.x;
    if (c >= EMB) return;
    int m = g_m[b];
    int base = b * MAXM * EMB + c;
    float Av[MAXM], Ov[MAXM];
    #pragma unroll
    for (int s = 0; s < MAXM; s++) {
        Av[s] = (s < m) ? g_A[base + s * EMB] : -3.4e38f;
        Ov[s] = (s < m) ? g_O[base + s * EMB] : 0.f;
    }
    float mx = Av[0];
    #pragma unroll
    for (int s = 1; s < MAXM; s++) mx = fmaxf(mx, Av[s]);
    float den = 0.f;
    #pragma unroll
    for (int s = 0; s < MAXM; s++) { Av[s] = expf(Av[s] - mx); den += Av[s]; }
    float inv = 1.f / den;
    #pragma unroll
    for (int s = 0; s < MAXM; s++) {
        float la = (s < m) ? fmaxf(Ov[s] * (Av[s] * inv), 0.f) : 0.f;
        g_LA[base + s * EMB] = la;
    }
}

// ---------------- K4: MLP layer 1 — 256 threads, c-split, MCIC=11 (grid 15x44x2) ----------------
__global__ void __launch_bounds__(256, 5) k_mlp1() {
    int g0 = blockIdx.x * ROWS;
    int ciBeg = blockIdx.y * MCIC;
    __shared__ __align__(16) float xs[MCIC][ROWS];
    int tid = threadIdx.x;
    if (tid < ROWS * MCIC) {
        int i = tid >> 4, s = tid & 15;
        xs[i][s] = g_LA[(g0 + s) * EMB + ciBeg + i];
    }
    __syncthreads();
    if (tid >= CHALF) return;
    int c = blockIdx.z * CHALF + tid;
    unsigned xsB = (unsigned)__cvta_generic_to_shared(&xs[0][0]);
    unsigned long long acc[8];
    #pragma unroll
    for (int p = 0; p < 8; p++) acc[p] = 0ull;
    const float* wp = &g_W1t[ciBeg * EMB + c];
    float wv[MCIC];
    #pragma unroll
    for (int k = 0; k < MCIC; k++) wv[k] = wp[k * EMB];
    #pragma unroll
    for (int k = 0; k < MCIC; k++) {
        unsigned long long w2;
        BCAST2(w2, wv[k]);
        unsigned rowB = xsB + k * (ROWS * 4);
        #pragma unroll
        for (int j = 0; j < 4; j++) {
            unsigned long long x0, x1;
            LDS2x64(x0, x1, rowB + j * 16);
            FMA2(acc[j * 2],     x0, w2);
            FMA2(acc[j * 2 + 1], x1, w2);
        }
    }
    #pragma unroll
    for (int p = 0; p < 8; p++) {
        float lo, hi;
        UNPACK2(lo, hi, acc[p]);
        atomicAdd(&g_Y1[(g0 + p * 2) * EMB + c], lo);
        atomicAdd(&g_Y1[(g0 + p * 2 + 1) * EMB + c], hi);
    }
}

// ---------------- K5: MLP layer 2 + ddg scale — 256 threads, c-split, MCIC=11 ----------------
__global__ void __launch_bounds__(256, 5) k_mlp2(const float* __restrict__ b1,
                                                 const float* __restrict__ wddg) {
    int g0 = blockIdx.x * ROWS;
    int ciBeg = blockIdx.y * MCIC;
    __shared__ __align__(16) float xs[MCIC][ROWS];
    int tid = threadIdx.x;
    if (tid < ROWS * MCIC) {
        int i = tid >> 4, s = tid & 15;
        int g = g0 + s; float v = 0.f;
        if (g < NSLOT)       v = fmaxf(g_Y1[g * EMB + ciBeg + i], 0.f);
        else if (g == NSLOT) v = fmaxf(b1[ciBeg + i], 0.f);    // bg: y1 = b1
        xs[i][s] = v;
    }
    __syncthreads();
    if (tid >= CHALF) return;
    int c = blockIdx.z * CHALF + tid;
    unsigned xsB = (unsigned)__cvta_generic_to_shared(&xs[0][0]);
    unsigned long long acc[8];
    #pragma unroll
    for (int p = 0; p < 8; p++) acc[p] = 0ull;
    const float* wp = &g_W2t[ciBeg * EMB + c];
    float wv[MCIC];
    #pragma unroll
    for (int k = 0; k < MCIC; k++) wv[k] = wp[k * EMB];
    #pragma unroll
    for (int k = 0; k < MCIC; k++) {
        unsigned long long w2;
        BCAST2(w2, wv[k]);
        unsigned rowB = xsB + k * (ROWS * 4);
        #pragma unroll
        for (int j = 0; j < 4; j++) {
            unsigned long long x0, x1;
            LDS2x64(x0, x1, rowB + j * 16);
            FMA2(acc[j * 2],     x0, w2);
            FMA2(acc[j * 2 + 1], x1, w2);
        }
    }
    float wd = wddg[0];
    #pragma unroll
    for (int p = 0; p < 8; p++) {
        float lo, hi;
        UNPACK2(lo, hi, acc[p]);
        int ga = g0 + p * 2, gb = g0 + p * 2 + 1;
        if (ga <= NSLOT) atomicAdd(&g_DDG[ga * EMB + c], wd * lo);
        if (gb <= NSLOT) atomicAdd(&g_DDG[gb * EMB + c], wd * hi);
    }
}

// ---------------- K6: scoring (256 threads: 2 gather rounds) ----------------
__global__ void k_score(const int* __restrict__ sortcery, const int* __restrict__ seqs,
                        const int* __restrict__ mut_pos, float* __restrict__ out) {
    int s = blockIdx.x, b = blockIdx.y, tid = threadIdx.x;
    int mp = mut_pos[b];
    int spos = sortcery[((size_t)(b * NSEQ + s)) * NN + mp];
    int wpos = seqs[b * NN + mp];
    float part = 0.f;
    for (int j = tid; j < NN; j += 256) {
        int rowB = g_row[b * NN + j];
        int as = sortcery[((size_t)(b * NSEQ + s)) * NN + j];
        int aw = seqs[b * NN + j];
        part += g_DDG[rowB + spos * HP + as]
              - g_DDG[rowB + wpos * HP + aw];
    }
    __shared__ float red[256];
    red[tid] = part;
    __syncthreads();
    for (int off = 128; off > 0; off >>= 1) {
        if (tid < off) red[tid] += red[tid + off];
        __syncthreads();
    }
    if (tid == 0) out[b * NSEQ + s] = red[0];
}

// ---------------- launch ----------------
extern "C" void kernel_launch(void* const* d_in, const int* in_sizes, int n_in,
                              void* d_out, int out_size) {
    const float* etab     = (const float*)d_in[0];
    const int*   E_idx    = (const int*)  d_in[1];
    const int*   sortcery = (const int*)  d_in[2];
    const int*   seqs     = (const int*)  d_in[3];
    const int*   mut_pos  = (const int*)  d_in[4];
    const float* Wf       = (const float*)d_in[6];
    const float* bf       = (const float*)d_in[7];
    const float* Wa       = (const float*)d_in[8];
    const float* ba       = (const float*)d_in[9];
    const float* W1       = (const float*)d_in[10];
    const float* b1       = (const float*)d_in[11];
    const float* W2       = (const float*)d_in[12];
    const float* b2       = (const float*)d_in[13];
    const float* wddg     = (const float*)d_in[14];
    const float* bddg     = (const float*)d_in[15];
    float* out = (float*)d_out;

    k_prep<<<PREP_BLOCKS, 256>>>(Wf, Wa, W1, W2, etab, E_idx, mut_pos,
                                 bf, ba, b1, b2, wddg, bddg);
    k_conv<<<dim3(15, KSZ, NCH * 2), 256>>>();
    k_softmax<<<dim3(BB, 4), 128>>>();
    k_mlp1<<<dim3(15, MNCH, 2), 256>>>();
    k_mlp2<<<dim3(16, MNCH, 2), 256>>>(b1, wddg);
    k_score<<<dim3(NSEQ, BB), 256>>>(sortcery, seqs, mut_pos, out);
}

// round 16
// speedup vs baseline: 1.1542x; 1.1542x over previous
#include <cuda_runtime.h>
#include <cstdint>

#define BB 8
#define NN 512
#define KK 30
#define HAA 20
#define HP 22
#define EMB 484
#define KSZ 9
#define MAXM 30
#define NSLOT (BB*MAXM)      // 240
#define NSEQ 99
#define CIT 4356             // EMB*KSZ
#define CIC 22               // conv ci chunk
#define NCH 22               // conv chunks
#define MCIC 22              // mlp ci chunk
#define MNCH 22              // mlp chunks
#define PAIRS 16             // pairs per conv block
#define ROWS 16              // rows per mlp block
#define CHALF 242            // c-split: 2 x 242 = 484

// ---- f32x2 packed helpers (sm_10x) ----
#define FMA2(acc, x2, w2) asm("fma.rn.f32x2 %0, %1, %2, %0;" : "+l"(acc) : "l"(x2), "l"(w2))
#define BCAST2(d, w)      asm("mov.b64 %0, {%1, %1};" : "=l"(d) : "f"(w))
#define UNPACK2(lo, hi, s) asm("mov.b64 {%0, %1}, %2;" : "=f"(lo), "=f"(hi) : "l"(s))
#define LDS2x64(a, b, addr) asm("ld.shared.v2.u64 {%0, %1}, [%2];" : "=l"(a), "=l"(b) : "r"(addr))
// PDL: wait for stream-order predecessor before reading its outputs
#define GRID_WAIT() asm volatile("griddepcontrol.wait;" ::: "memory")

// ---------------- scratch (static device globals; no allocation) ----------------
__device__ float g_Wtf[CIT*EMB];     // [(ci*9+t)][c]
__device__ float g_Wta[CIT*EMB];
__device__ float g_W1t[EMB*EMB];     // [ci][c]
__device__ float g_W2t[EMB*EMB];
__device__ float g_linv[NSLOT*EMB];
__device__ float g_O[NSLOT*EMB];
__device__ float g_A[NSLOT*EMB];
__device__ float g_LA[NSLOT*EMB];
__device__ float g_Y1[NSLOT*EMB];
__device__ float g_DDG[(NSLOT+1)*EMB];
__device__ int   g_row[BB*NN];             // dense pos -> rowBase (*EMB, bg row if none)
__device__ int   g_m[BB];
__device__ int   g_cntBT[BB*KSZ];          // per-(b,tap) pair count
__device__ int   g_pairIn[BB*KSZ*MAXM];
__device__ int   g_pairOut[BB*KSZ*MAXM];

// ---------------- K1 fused: transposes + parallel scatter + Y1/DDG init ----------------
#define TB0 2192
#define TB1 4384
#define TB2 4640
#define TB3 4896
#define SCAT_END (TB3 + BB)
#define INIT_END (SCAT_END + NSLOT + 1)
#define PREP_BLOCKS INIT_END

__global__ void k_prep(const float* __restrict__ Wf, const float* __restrict__ Wa,
                       const float* __restrict__ W1, const float* __restrict__ W2,
                       const float* __restrict__ etab, const int* __restrict__ E_idx,
                       const int* __restrict__ mut_pos,
                       const float* __restrict__ b_f, const float* __restrict__ b_a,
                       const float* __restrict__ b1, const float* __restrict__ b2,
                       const float* __restrict__ wddg, const float* __restrict__ bddg) {
    int bx = blockIdx.x;
    int tid = threadIdx.x;

    if (bx >= SCAT_END) {
        int row = bx - SCAT_END;
        float wd = wddg[0], bd = bddg[0];
        for (int c = tid; c < EMB; c += 256) {
            float dinit = b2[c] * wd + bd;
            g_DDG[row * EMB + c] = dinit;
            if (row < NSLOT) g_Y1[row * EMB + c] = b1[c];
        }
        return;
    }

    if (bx < TB3) {
        __shared__ float tile[32][33];
        const float* src; float* dst; int C, xt, yt;
        if (bx < TB0)      { src = Wf; dst = g_Wtf; C = CIT; int i = bx;       xt = i % 137; yt = i / 137; }
        else if (bx < TB1) { src = Wa; dst = g_Wta; C = CIT; int i = bx - TB0; xt = i % 137; yt = i / 137; }
        else if (bx < TB2) { src = W1; dst = g_W1t; C = EMB; int i = bx - TB1; xt = i % 16;  yt = i / 16; }
        else               { src = W2; dst = g_W2t; C = EMB; int i = bx - TB2; xt = i % 16;  yt = i / 16; }
        int tx = tid & 31, ty = tid >> 5;
        int xBase = xt * 32, yBase = yt * 32;
        int x = xBase + tx;
        for (int j = ty; j < 32; j += 8) {
            int y = yBase + j;
            if (y < EMB && x < C) tile[j][tx] = src[y * C + x];
        }
        __syncthreads();
        int ox = yBase + tx;
        for (int j = ty; j < 32; j += 8) {
            int oy = xBase + j;
            if (oy < C && ox < EMB) dst[oy * EMB + ox] = tile[tx][j];
        }
        return;
    }

    // ---- scatter part (256 threads, one block per batch) ----
    int b = bx - TB3;
    __shared__ int win[NN];
    __shared__ int slotArr[NN];
    __shared__ unsigned msk[16];
    __shared__ int cpre[16];
    __shared__ int sPos[MAXM], sSrc[MAXM];
    __shared__ int sM;

    win[tid] = -1; win[tid + 256] = -1;
    if (tid < KSZ) g_cntBT[b * KSZ + tid] = 0;
    __syncthreads();

    int mp = mut_pos[b];
    const int* nb = &E_idx[(b * NN + mp) * KK];
    if (tid < KK) atomicMax(&win[nb[tid]], tid);   // last j wins == max j wins
    __syncthreads();

    int warp = tid >> 5, lane = tid & 31;
    #pragma unroll
    for (int h = 0; h < 2; h++) {
        int chunk = warp + h * 8;
        int l = chunk * 32 + lane;
        unsigned bal = __ballot_sync(0xffffffffu, win[l] >= 0);
        if (lane == 0) msk[chunk] = bal;
    }
    __syncthreads();
    if (tid == 0) {
        int acc = 0;
        for (int i = 0; i < 16; i++) { cpre[i] = acc; acc += __popc(msk[i]); }
        sM = acc; g_m[b] = acc;
    }
    __syncthreads();
    #pragma unroll
    for (int h = 0; h < 2; h++) {
        int chunk = warp + h * 8;
        int l = chunk * 32 + lane;
        int w = win[l];
        int slot = -1;
        if (w >= 0) {
            slot = cpre[chunk] + __popc(msk[chunk] & ((1u << lane) - 1));
            sPos[slot] = l; sSrc[slot] = w;
        }
        slotArr[l] = slot;
        g_row[b * NN + l] = ((slot >= 0) ? (b * MAXM + slot) : NSLOT) * EMB;
    }
    __syncthreads();

    int m = sM;
    for (int c = tid; c < EMB; c += 256) {
        int h0 = c / HP, h1 = c % HP;
        float bfv = b_f[c], bav = b_a[c];
        bool valid = (h0 < HAA) && (h1 < HAA);
        int srcc = h0 * HAA + h1;
        for (int s = 0; s < m; s++) {
            float v = 0.f;
            if (valid)
                v = etab[(size_t)((b * NN + mp) * KK + sSrc[s]) * (HAA * HAA) + srcc];
            int g = (b * MAXM + s) * EMB + c;
            g_linv[g] = v; g_O[g] = bfv; g_A[g] = bav;
        }
    }
    for (int q = tid; q < m * KSZ; q += 256) {
        int s = q / KSZ, t = q % KSZ;
        int p = sPos[s] + t - 4;              // y[l] += W[t] * x[l+t-4]
        if (p >= 0 && p < NN) {
            int si = slotArr[p];
            if (si >= 0) {
                int idx = atomicAdd(&g_cntBT[b * KSZ + t], 1);
                g_pairIn[(b * KSZ + t) * MAXM + idx]  = b * MAXM + si;
                g_pairOut[(b * KSZ + t) * MAXM + idx] = b * MAXM + s;
            }
        }
    }
}

// ---------------- K2: conv — 256 threads, c-split, f32x2 + v2.u64 LDS ----------------
// grid: (pairBlocks, KSZ, NCH*2); z = chunk*2 + cHalf
__global__ void __launch_bounds__(256, 4) k_conv() {
    int t = blockIdx.y;
    int chunk = blockIdx.z >> 1;
    int cHalf = blockIdx.z & 1;
    __shared__ __align__(16) float xs[CIC][PAIRS];   // [k][pair], 64B rows
    __shared__ int pre[BB + 1];
    __shared__ int pin[PAIRS], pout[PAIRS];
    int tid = threadIdx.x;
    GRID_WAIT();                                    // wait for k_prep outputs
    if (tid == 0) {
        int acc = 0;
        #pragma unroll
        for (int b = 0; b < BB; b++) { pre[b] = acc; acc += g_cntBT[b * KSZ + t]; }
        pre[BB] = acc;
    }
    __syncthreads();
    int total = pre[BB];
    int p0 = blockIdx.x * PAIRS;
    if (p0 >= total) return;
    if (tid < PAIRS) {
        int gi = p0 + tid;
        if (gi < total) {
            int b = 0;
            while (gi >= pre[b + 1]) b++;
            int idx = gi - pre[b];
            pin[tid]  = g_pairIn[(b * KSZ + t) * MAXM + idx];
            pout[tid] = g_pairOut[(b * KSZ + t) * MAXM + idx];
        } else { pin[tid] = -1; pout[tid] = -1; }
    }
    __syncthreads();
    int ciBeg = chunk * CIC;
    for (int idx = tid; idx < PAIRS * CIC; idx += 256) {
        int i = idx >> 4, s = idx & 15;
        int g = pin[s];
        xs[i][s] = (g >= 0) ? g_linv[g * EMB + ciBeg + i] : 0.f;
    }
    __syncthreads();
    if (tid >= CHALF) return;
    int c = cHalf * CHALF + tid;
    unsigned xsB = (unsigned)__cvta_generic_to_shared(&xs[0][0]);
    unsigned long long aO[8], aA[8];
    #pragma unroll
    for (int p = 0; p < 8; p++) { aO[p] = 0ull; aA[p] = 0ull; }
    const float* wf = &g_Wtf[(ciBeg * KSZ + t) * EMB + c];
    const float* wa = &g_Wta[(ciBeg * KSZ + t) * EMB + c];
    #pragma unroll
    for (int g = 0; g < CIC; g += 11) {
        float wfv[11], wav[11];
        #pragma unroll
        for (int k = 0; k < 11; k++) {
            wfv[k] = wf[(g + k) * (KSZ * EMB)];
            wav[k] = wa[(g + k) * (KSZ * EMB)];
        }
        #pragma unroll
        for (int k = 0; k < 11; k++) {
            unsigned long long wf2, wa2;
            BCAST2(wf2, wfv[k]);
            BCAST2(wa2, wav[k]);
            unsigned rowB = xsB + (g + k) * (PAIRS * 4);
            #pragma unroll
            for (int j = 0; j < 4; j++) {
                unsigned long long x0, x1;
                LDS2x64(x0, x1, rowB + j * 16);
                FMA2(aO[j * 2],     x0, wf2);
                FMA2(aO[j * 2 + 1], x1, wf2);
                FMA2(aA[j * 2],     x0, wa2);
                FMA2(aA[j * 2 + 1], x1, wa2);
            }
        }
    }
    #pragma unroll
    for (int p = 0; p < 8; p++) {
        float olo, ohi, alo, ahi;
        UNPACK2(olo, ohi, aO[p]);
        UNPACK2(alo, ahi, aA[p]);
        int g0 = pout[p * 2], g1 = pout[p * 2 + 1];
        if (g0 >= 0) { atomicAdd(&g_O[g0 * EMB + c], olo); atomicAdd(&g_A[g0 * EMB + c], alo); }
        if (g1 >= 0) { atomicAdd(&g_O[g1 * EMB + c], ohi); atomicAdd(&g_A[g1 * EMB + c], ahi); }
    }
}

// ---------------- K3: register-resident masked softmax -> relu(la) ----------------
__global__ void k_softmax() {
    int b = blockIdx.x;
    int c = blockIdx.y * 128 + threadIdx.x;
    GRID_WAIT();                                    // wait for k_conv O/A
    if (c >= EMB) return;
    int m = g_m[b];
    int base = b * MAXM * EMB + c;
    float Av[MAXM], Ov[MAXM];
    #pragma unroll
    for (int s = 0; s < MAXM; s++) {
        Av[s] = (s < m) ? g_A[base + s * EMB] : -3.4e38f;
        Ov[s] = (s < m) ? g_O[base + s * EMB] : 0.f;
    }
    float mx = Av[0];
    #pragma unroll
    for (int s = 1; s < MAXM; s++) mx = fmaxf(mx, Av[s]);
    float den = 0.f;
    #pragma unroll
    for (int s = 0; s < MAXM; s++) { Av[s] = expf(Av[s] - mx); den += Av[s]; }
    float inv = 1.f / den;
    #pragma unroll
    for (int s = 0; s < MAXM; s++) {
        float la = (s < m) ? fmaxf(Ov[s] * (Av[s] * inv), 0.f) : 0.f;
        g_LA[base + s * EMB] = la;
    }
}

// ---------------- K4: MLP layer 1 — 256 threads, c-split, MCIC=22 ----------------
__global__ void __launch_bounds__(256, 4) k_mlp1() {
    int g0 = blockIdx.x * ROWS;
    int ciBeg = blockIdx.y * MCIC;
    __shared__ __align__(16) float xs[MCIC][ROWS];
    int tid = threadIdx.x;
    GRID_WAIT();                                    // wait for k_softmax LA
    for (int idx = tid; idx < ROWS * MCIC; idx += 256) {
        int i = idx >> 4, s = idx & 15;
        xs[i][s] = g_LA[(g0 + s) * EMB + ciBeg + i];
    }
    __syncthreads();
    if (tid >= CHALF) return;
    int c = blockIdx.z * CHALF + tid;
    unsigned xsB = (unsigned)__cvta_generic_to_shared(&xs[0][0]);
    unsigned long long acc[8];
    #pragma unroll
    for (int p = 0; p < 8; p++) acc[p] = 0ull;
    const float* wp = &g_W1t[ciBeg * EMB + c];
    #pragma unroll
    for (int g = 0; g < MCIC; g += 11) {
        float wv[11];
        #pragma unroll
        for (int k = 0; k < 11; k++) wv[k] = wp[(g + k) * EMB];
        #pragma unroll
        for (int k = 0; k < 11; k++) {
            unsigned long long w2;
            BCAST2(w2, wv[k]);
            unsigned rowB = xsB + (g + k) * (ROWS * 4);
            #pragma unroll
            for (int j = 0; j < 4; j++) {
                unsigned long long x0, x1;
                LDS2x64(x0, x1, rowB + j * 16);
                FMA2(acc[j * 2],     x0, w2);
                FMA2(acc[j * 2 + 1], x1, w2);
            }
        }
    }
    #pragma unroll
    for (int p = 0; p < 8; p++) {
        float lo, hi;
        UNPACK2(lo, hi, acc[p]);
        atomicAdd(&g_Y1[(g0 + p * 2) * EMB + c], lo);
        atomicAdd(&g_Y1[(g0 + p * 2 + 1) * EMB + c], hi);
    }
}

// ---------------- K5: MLP layer 2 + ddg scale — 256 threads, c-split, MCIC=22 ----------------
__global__ void __launch_bounds__(256, 4) k_mlp2(const float* __restrict__ b1,
                                                 const float* __restrict__ wddg) {
    int g0 = blockIdx.x * ROWS;
    int ciBeg = blockIdx.y * MCIC;
    __shared__ __align__(16) float xs[MCIC][ROWS];
    int tid = threadIdx.x;
    GRID_WAIT();                                    // wait for k_mlp1 Y1
    for (int idx = tid; idx < ROWS * MCIC; idx += 256) {
        int i = idx >> 4, s = idx & 15;
        int g = g0 + s; float v = 0.f;
        if (g < NSLOT)       v = fmaxf(g_Y1[g * EMB + ciBeg + i], 0.f);
        else if (g == NSLOT) v = fmaxf(b1[ciBeg + i], 0.f);    // bg: y1 = b1
        xs[i][s] = v;
    }
    __syncthreads();
    if (tid >= CHALF) return;
    int c = blockIdx.z * CHALF + tid;
    unsigned xsB = (unsigned)__cvta_generic_to_shared(&xs[0][0]);
    unsigned long long acc[8];
    #pragma unroll
    for (int p = 0; p < 8; p++) acc[p] = 0ull;
    const float* wp = &g_W2t[ciBeg * EMB + c];
    #pragma unroll
    for (int g = 0; g < MCIC; g += 11) {
        float wv[11];
        #pragma unroll
        for (int k = 0; k < 11; k++) wv[k] = wp[(g + k) * EMB];
        #pragma unroll
        for (int k = 0; k < 11; k++) {
            unsigned long long w2;
            BCAST2(w2, wv[k]);
            unsigned rowB = xsB + (g + k) * (ROWS * 4);
            #pragma unroll
            for (int j = 0; j < 4; j++) {
                unsigned long long x0, x1;
                LDS2x64(x0, x1, rowB + j * 16);
                FMA2(acc[j * 2],     x0, w2);
                FMA2(acc[j * 2 + 1], x1, w2);
            }
        }
    }
    float wd = wddg[0];
    #pragma unroll
    for (int p = 0; p < 8; p++) {
        float lo, hi;
        UNPACK2(lo, hi, acc[p]);
        int ga = g0 + p * 2, gb = g0 + p * 2 + 1;
        if (ga <= NSLOT) atomicAdd(&g_DDG[ga * EMB + c], wd * lo);
        if (gb <= NSLOT) atomicAdd(&g_DDG[gb * EMB + c], wd * hi);
    }
}

// ---------------- K6: scoring ----------------
__global__ void k_score(const int* __restrict__ sortcery, const int* __restrict__ seqs,
                        const int* __restrict__ mut_pos, float* __restrict__ out) {
    int s = blockIdx.x, b = blockIdx.y, tid = threadIdx.x;
    // preload index data (pure inputs, always ready) before waiting on mlp2's DDG
    int mp = mut_pos[b];
    int spos = sortcery[((size_t)(b * NSEQ + s)) * NN + mp];
    int wpos = seqs[b * NN + mp];
    GRID_WAIT();                                    // wait for k_mlp2 DDG
    float part = 0.f;
    for (int j = tid; j < NN; j += 128) {
        int rowB = g_row[b * NN + j];
        int as = sortcery[((size_t)(b * NSEQ + s)) * NN + j];
        int aw = seqs[b * NN + j];
        part += g_DDG[rowB + spos * HP + as]
              - g_DDG[rowB + wpos * HP + aw];
    }
    __shared__ float red[128];
    red[tid] = part;
    __syncthreads();
    for (int off = 64; off > 0; off >>= 1) {
        if (tid < off) red[tid] += red[tid + off];
        __syncthreads();
    }
    if (tid == 0) out[b * NSEQ + s] = red[0];
}

// ---------------- launch (PDL on all dependent kernels) ----------------
static inline void launch_pdl(void* fn, dim3 grid, dim3 block, void** args) {
    cudaLaunchConfig_t cfg = {};
    cudaLaunchAttribute attr[1];
    attr[0].id = cudaLaunchAttributeProgrammaticStreamSerialization;
    attr[0].val.programmaticStreamSerializationAllowed = 1;
    cfg.gridDim = grid;
    cfg.blockDim = block;
    cfg.dynamicSmemBytes = 0;
    cfg.stream = 0;
    cfg.attrs = attr;
    cfg.numAttrs = 1;
    cudaLaunchKernelExC(&cfg, fn, args);
}

extern "C" void kernel_launch(void* const* d_in, const int* in_sizes, int n_in,
                              void* d_out, int out_size) {
    const float* etab     = (const float*)d_in[0];
    const int*   E_idx    = (const int*)  d_in[1];
    const int*   sortcery = (const int*)  d_in[2];
    const int*   seqs     = (const int*)  d_in[3];
    const int*   mut_pos  = (const int*)  d_in[4];
    const float* Wf       = (const float*)d_in[6];
    const float* bf       = (const float*)d_in[7];
    const float* Wa       = (const float*)d_in[8];
    const float* ba       = (const float*)d_in[9];
    const float* W1       = (const float*)d_in[10];
    const float* b1       = (const float*)d_in[11];
    const float* W2       = (const float*)d_in[12];
    const float* b2       = (const float*)d_in[13];
    const float* wddg     = (const float*)d_in[14];
    const float* bddg     = (const float*)d_in[15];
    float* out = (float*)d_out;

    k_prep<<<PREP_BLOCKS, 256>>>(Wf, Wa, W1, W2, etab, E_idx, mut_pos,
                                 bf, ba, b1, b2, wddg, bddg);

    {   // k_conv
        void* args[] = {};
        launch_pdl((void*)k_conv, dim3(15, KSZ, NCH * 2), dim3(256), args);
    }
    {   // k_softmax
        void* args[] = {};
        launch_pdl((void*)k_softmax, dim3(BB, 4), dim3(128), args);
    }
    {   // k_mlp1
        void* args[] = {};
        launch_pdl((void*)k_mlp1, dim3(15, MNCH, 2), dim3(256), args);
    }
    {   // k_mlp2
        void* args[] = {(void*)&b1, (void*)&wddg};
        launch_pdl((void*)k_mlp2, dim3(16, MNCH, 2), dim3(256), args);
    }
    {   // k_score
        void* args[] = {(void*)&sortcery, (void*)&seqs, (void*)&mut_pos, (void*)&out};
        launch_pdl((void*)k_score, dim3(NSEQ, BB), dim3(128), args);
    }
}